// round 13
// baseline (speedup 1.0000x reference)
#include <cuda_runtime.h>

#define NPED    4096
#define NBLK    512
#define NTHR    256

#define DT        0.4f
#define K_ATTR    2.0f
#define PED_SPEED 1.0f
#define INV_MASS  (1.0f/60.0f)
#define EPS       1e-8f
#define A_COST    5.0f
#define B_COST    2.0f
// 10*exp((0.6-dist)/0.71) = exp2(C1 - dist*C2)
#define C2_EXP 2.0319648f
#define C1_EXP 4.5411053f

__device__ unsigned int g_ticket = 0;       // reset by last block each launch
__device__ float g_dev_part[NBLK];

__device__ __forceinline__ float ex2_approx(float x) {
    float r; asm("ex2.approx.f32 %0, %1;" : "=f"(r) : "f"(x)); return r;
}
__device__ __forceinline__ float rsqrt_approx(float x) {
    float r; asm("rsqrt.approx.f32 %0, %1;" : "=f"(r) : "f"(x)); return r;
}

// Fused kernel: stacked copy + forces + propagation + cost.
// 512 blocks x 256 threads; warp w owns pedestrian i = b*8 + w.
// Positions packed 2-per-float4 in smem; inner loop does 2 pairs per LDS.128.
__global__ void __launch_bounds__(NTHR) fused_kernel(
    const float* __restrict__ state,       // [N,4]
    const float* __restrict__ goal,        // [N,2]
    const float* __restrict__ stacked_in,  // [N*4]
    const float* __restrict__ observed,    // [N,4]
    const float* __restrict__ cost_in,     // [1]
    float* __restrict__ out_state,         // [N,4]
    float* __restrict__ out_cost,          // [1]
    float* __restrict__ out_stacked)       // [2*N*4] (4B-aligned only)
{
    __shared__ float4 spos4[NPED / 2];     // 32KB: {x0,y0,x1,y1} pairs
    __shared__ float  s_dev[8];
    __shared__ int    s_last;
    __shared__ float  s_red[16];

    const int tid  = threadIdx.x;
    const int lane = tid & 31;
    const int w    = tid >> 5;
    const int i    = blockIdx.x * 8 + w;

    // fused concat copy: g in [0, 16384) -> blocks 0..63 cover both halves
    {
        int g = blockIdx.x * NTHR + tid;
        if (g < NPED * 4) {
            out_stacked[g]            = stacked_in[g];
            out_stacked[NPED * 4 + g] = state[g];
        }
    }

    // one-shot stage: pack positions of rows 2k, 2k+1 into one float4
    const float4* __restrict__ srow = (const float4*)state;   // row = {px,py,vx,vy}
    #pragma unroll
    for (int k = tid; k < NPED / 2; k += NTHR) {
        float4 a = srow[2 * k];
        float4 b = srow[2 * k + 1];
        spos4[k] = make_float4(a.x, a.y, b.x, b.y);
    }
    __syncthreads();

    const float4 si = srow[i];
    const float xi = si.x, yi = si.y;

    float fx0 = 0.0f, fy0 = 0.0f, fx1 = 0.0f, fy1 = 0.0f;

    #pragma unroll 4
    for (int jj = lane; jj < NPED / 2; jj += 32) {
        float4 pj = spos4[jj];                    // 2 positions per LDS.128
        // pair A
        float dxa = xi - pj.x;
        float dya = yi - pj.y;
        float d2a = fmaf(dxa, dxa, fmaf(dya, dya, EPS));
        float rda = rsqrt_approx(d2a);
        float dia = d2a * rda;
        float cfa = ex2_approx(fmaf(dia, -C2_EXP, C1_EXP)) * rda;
        fx0 = fmaf(cfa, dxa, fx0);
        fy0 = fmaf(cfa, dya, fy0);
        // pair B
        float dxb = xi - pj.z;
        float dyb = yi - pj.w;
        float d2b = fmaf(dxb, dxb, fmaf(dyb, dyb, EPS));
        float rdb = rsqrt_approx(d2b);
        float dib = d2b * rdb;
        float cfb = ex2_approx(fmaf(dib, -C2_EXP, C1_EXP)) * rdb;
        fx1 = fmaf(cfb, dxb, fx1);
        fy1 = fmaf(cfb, dyb, fy1);
        // j==i: dx=dy=0 exactly -> contributes exactly 0
    }
    float fx = fx0 + fx1;
    float fy = fy0 + fy1;

    // warp reduction
    #pragma unroll
    for (int o = 16; o > 0; o >>= 1) {
        fx += __shfl_xor_sync(0xffffffffu, fx, o);
        fy += __shfl_xor_sync(0xffffffffu, fy, o);
    }

    if (lane == 0) {
        const float vx = si.z, vy = si.w;
        const float2 gl = ((const float2*)goal)[i];

        float tgx = gl.x - xi, tgy = gl.y - yi;
        float dg2 = fmaf(tgx, tgx, fmaf(tgy, tgy, EPS));
        float rdg = rsqrt_approx(dg2);
        float afx = K_ATTR * fmaf(PED_SPEED * tgx, rdg, -vx);
        float afy = K_ATTR * fmaf(PED_SPEED * tgy, rdg, -vy);

        float Fx = fmaf(fx, INV_MASS, afx);
        float Fy = fmaf(fy, INV_MASS, afy);

        float npx = xi + vx * DT + 0.5f * Fx * (DT * DT);
        float npy = yi + vy * DT + 0.5f * Fy * (DT * DT);
        float nvx = fmaf(Fx, DT, vx);
        float nvy = fmaf(Fy, DT, vy);
        float spd = sqrtf(fmaf(nvx, nvx, fmaf(nvy, nvy, EPS)));
        float scale = fminf(1.0f, PED_SPEED / spd);

        ((float4*)out_state)[i] = make_float4(npx, npy, nvx * scale, nvy * scale);

        // local deviation contribution (peds = rows 1..N-1)
        float dev = 0.0f;
        if (i > 0) {
            float ox = observed[i*4 + 0];
            float oy = observed[i*4 + 1];
            float ddx = npx - ox, ddy = npy - oy;
            dev = sqrtf(fmaf(ddx, ddx, fmaf(ddy, ddy, EPS)));
        }
        s_dev[w] = dev;
    }
    __syncthreads();

    if (tid == 0) {
        float d = 0.0f;
        #pragma unroll
        for (int k = 0; k < 8; k++) d += s_dev[k];
        g_dev_part[blockIdx.x] = d;
    }

    // make this block's global writes visible, then take a ticket
    __threadfence();
    if (tid == 0) {
        unsigned int t = atomicAdd(&g_ticket, 1u);
        s_last = (t == NBLK - 1) ? 1 : 0;
    }
    __syncthreads();

    // ---- last block finalizes the cost ----
    if (s_last) {
        __threadfence();
        const float rx = __ldcg(&out_state[0]);
        const float ry = __ldcg(&out_state[1]);

        // deterministic sum of per-block deviation partials
        float dev = 0.0f;
        #pragma unroll
        for (int k = 0; k < NBLK / NTHR; k++)
            dev += __ldcg(&g_dev_part[tid + k * NTHR]);

        // blame over peds 1..N-1
        float blm = 0.0f;
        #pragma unroll 4
        for (int p = 1 + tid; p < NPED; p += NTHR) {
            float2 q = __ldcg((const float2*)(out_state + p * 4));
            float bx = q.x - rx, by = q.y - ry;
            float d = sqrtf(fmaf(bx, bx, fmaf(by, by, EPS)));
            blm += ex2_approx(-d * 1.4426950f);   // exp(-d), E_COST=1
        }

        #pragma unroll
        for (int o = 16; o > 0; o >>= 1) {
            dev += __shfl_xor_sync(0xffffffffu, dev, o);
            blm += __shfl_xor_sync(0xffffffffu, blm, o);
        }
        if (lane == 0) { s_red[w] = dev; s_red[8 + w] = blm; }
        __syncthreads();

        if (tid == 0) {
            float devt = 0.0f, blmt = 0.0f;
            #pragma unroll
            for (int k = 0; k < 8; k++) { devt += s_red[k]; blmt += s_red[8 + k]; }
            float ix = state[0], iy = state[1];
            float gx = goal[0],  gy = goal[1];
            float d1x = ix - gx, d1y = iy - gy;
            float d2x = rx - gx, d2y = ry - gy;
            float pg = sqrtf(fmaf(d1x, d1x, fmaf(d1y, d1y, EPS)))
                     - sqrtf(fmaf(d2x, d2x, fmaf(d2y, d2y, EPS)));
            out_cost[0] = cost_in[0] + A_COST * devt + B_COST * blmt - pg;
            g_ticket = 0;   // reset for next graph replay
            __threadfence();
        }
    }
}

extern "C" void kernel_launch(void* const* d_in, const int* in_sizes, int n_in,
                              void* d_out, int out_size) {
    const float* state      = (const float*)d_in[0];
    const float* cost_in    = (const float*)d_in[1];
    const float* stacked_in = (const float*)d_in[2];
    const float* goal       = (const float*)d_in[3];
    const float* observed   = (const float*)d_in[4];

    float* out = (float*)d_out;
    float* out_state   = out;
    float* out_cost    = out + NPED*4;
    float* out_stacked = out + NPED*4 + 1;

    fused_kernel<<<NBLK, NTHR>>>(state, goal, stacked_in, observed, cost_in,
                                 out_state, out_cost, out_stacked);
}

// round 14
// speedup vs baseline: 1.2182x; 1.2182x over previous
#include <cuda_runtime.h>

#define NPED  4096
#define TILE  2048          // float2 per smem tile (16KB)
#define NBLKB 32            // cost-partial blocks

#define DT        0.4f
#define K_ATTR    2.0f
#define PED_SPEED 1.0f
#define INV_MASS  (1.0f/60.0f)
#define EPS       1e-8f
#define A_COST    5.0f
#define B_COST    2.0f
// 10*exp((0.6-dist)/0.71) = exp2(C1 - dist*C2)
#define C2_EXP 2.0319648f
#define C1_EXP 4.5411053f

__device__ float g_dev_part[NBLKB];
__device__ float g_blm_part[NBLKB];

__device__ __forceinline__ float ex2_approx(float x) {
    float r; asm("ex2.approx.f32 %0, %1;" : "=f"(r) : "f"(x)); return r;
}
__device__ __forceinline__ float rsqrt_approx(float x) {
    float r; asm("rsqrt.approx.f32 %0, %1;" : "=f"(r) : "f"(x)); return r;
}

// Kernel A: stacked copy + forces + propagation (R2-proven shape).
// 512 blocks x 256 threads; warp w of block b owns pedestrian i = b*8+w.
__global__ void __launch_bounds__(256) forces_prop_stack_kernel(
    const float* __restrict__ state,       // [N,4]
    const float* __restrict__ goal,        // [N,2]
    const float* __restrict__ stacked_in,  // [N*4]
    float* __restrict__ out_state,         // [N,4]
    float* __restrict__ out_stacked)       // [2*N*4] (4B-aligned only)
{
    __shared__ float2 spos[TILE];

    const int tid  = threadIdx.x;
    const int lane = tid & 31;
    const int i    = blockIdx.x * 8 + (tid >> 5);

    // fused concat copy: blocks 0..63 cover 16384 floats each half
    {
        int g = blockIdx.x * 256 + tid;
        if (g < NPED * 4) {
            out_stacked[g]            = stacked_in[g];
            out_stacked[NPED * 4 + g] = state[g];
        }
    }

    const float4 si = ((const float4*)state)[i];
    const float xi = si.x, yi = si.y;

    float fx = 0.0f, fy = 0.0f;

    const float2* __restrict__ pos2 = (const float2*)state;  // row = {pos, vel}

    #pragma unroll
    for (int t = 0; t < NPED / TILE; t++) {
        #pragma unroll
        for (int k = tid; k < TILE; k += 256)
            spos[k] = pos2[(t * TILE + k) * 2];
        __syncthreads();

        #pragma unroll 4
        for (int jj = lane; jj < TILE; jj += 32) {
            float2 pj = spos[jj];
            float dx = xi - pj.x;
            float dy = yi - pj.y;
            float d2 = fmaf(dx, dx, fmaf(dy, dy, EPS));
            float rd = rsqrt_approx(d2);
            float dist = d2 * rd;                                   // sqrt(d2)
            float coef = ex2_approx(fmaf(dist, -C2_EXP, C1_EXP)) * rd;
            // j==i: dx=dy=0 exactly -> contributes exactly 0
            fx = fmaf(coef, dx, fx);
            fy = fmaf(coef, dy, fy);
        }
        __syncthreads();
    }

    // warp reduction
    #pragma unroll
    for (int o = 16; o > 0; o >>= 1) {
        fx += __shfl_xor_sync(0xffffffffu, fx, o);
        fy += __shfl_xor_sync(0xffffffffu, fy, o);
    }

    if (lane == 0) {
        const float vx = si.z, vy = si.w;
        const float2 gl = ((const float2*)goal)[i];

        float tgx = gl.x - xi, tgy = gl.y - yi;
        float dg2 = fmaf(tgx, tgx, fmaf(tgy, tgy, EPS));
        float rdg = rsqrt_approx(dg2);
        float afx = K_ATTR * fmaf(PED_SPEED * tgx, rdg, -vx);
        float afy = K_ATTR * fmaf(PED_SPEED * tgy, rdg, -vy);

        float Fx = fmaf(fx, INV_MASS, afx);
        float Fy = fmaf(fy, INV_MASS, afy);

        float npx = xi + vx * DT + 0.5f * Fx * (DT * DT);
        float npy = yi + vy * DT + 0.5f * Fy * (DT * DT);
        float nvx = fmaf(Fx, DT, vx);
        float nvy = fmaf(Fy, DT, vy);
        float spd = sqrtf(fmaf(nvx, nvx, fmaf(nvy, nvy, EPS)));
        float scale = fminf(1.0f, PED_SPEED / spd);

        ((float4*)out_state)[i] = make_float4(npx, npy, nvx * scale, nvy * scale);
    }
}

// Kernel B: cost partials. 32 blocks x 128 threads, one ped per thread.
__global__ void __launch_bounds__(128) cost_partial_kernel(
    const float* __restrict__ observed,    // [N,4]
    const float* __restrict__ out_state)   // [N,4]
{
    const int tid = threadIdx.x;
    const int p   = blockIdx.x * 128 + tid;
    const int lane = tid & 31;
    const int w    = tid >> 5;
    __shared__ float s_d[4], s_b[4];

    const float rx = out_state[0];
    const float ry = out_state[1];

    float dev = 0.0f, blm = 0.0f;
    if (p >= 1) {   // peds are rows 1..N-1
        float px = out_state[p*4 + 0];
        float py = out_state[p*4 + 1];
        float ox = observed[p*4 + 0];
        float oy = observed[p*4 + 1];
        float ddx = px - ox, ddy = py - oy;
        dev = sqrtf(fmaf(ddx, ddx, fmaf(ddy, ddy, EPS)));
        float bx = px - rx, by = py - ry;
        float d = sqrtf(fmaf(bx, bx, fmaf(by, by, EPS)));
        blm = ex2_approx(-d * 1.4426950f);   // exp(-d), E_COST=1
    }

    #pragma unroll
    for (int o = 16; o > 0; o >>= 1) {
        dev += __shfl_xor_sync(0xffffffffu, dev, o);
        blm += __shfl_xor_sync(0xffffffffu, blm, o);
    }
    if (lane == 0) { s_d[w] = dev; s_b[w] = blm; }
    __syncthreads();
    if (tid == 0) {
        g_dev_part[blockIdx.x] = s_d[0] + s_d[1] + s_d[2] + s_d[3];
        g_blm_part[blockIdx.x] = s_b[0] + s_b[1] + s_b[2] + s_b[3];
    }
}

// Kernel C: finalize cost. 1 block, 32 threads.
__global__ void __launch_bounds__(32) cost_final_kernel(
    const float* __restrict__ state,
    const float* __restrict__ goal,
    const float* __restrict__ cost_in,
    const float* __restrict__ out_state,
    float* __restrict__ cost_out)
{
    const int lane = threadIdx.x;
    float dev = g_dev_part[lane];
    float blm = g_blm_part[lane];
    #pragma unroll
    for (int o = 16; o > 0; o >>= 1) {
        dev += __shfl_xor_sync(0xffffffffu, dev, o);
        blm += __shfl_xor_sync(0xffffffffu, blm, o);
    }
    if (lane == 0) {
        float rx = out_state[0], ry = out_state[1];
        float ix = state[0], iy = state[1];
        float gx = goal[0],  gy = goal[1];
        float d1x = ix - gx, d1y = iy - gy;
        float d2x = rx - gx, d2y = ry - gy;
        float pg = sqrtf(fmaf(d1x, d1x, fmaf(d1y, d1y, EPS)))
                 - sqrtf(fmaf(d2x, d2x, fmaf(d2y, d2y, EPS)));
        cost_out[0] = cost_in[0] + A_COST * dev + B_COST * blm - pg;
    }
}

extern "C" void kernel_launch(void* const* d_in, const int* in_sizes, int n_in,
                              void* d_out, int out_size) {
    const float* state      = (const float*)d_in[0];
    const float* cost_in    = (const float*)d_in[1];
    const float* stacked_in = (const float*)d_in[2];
    const float* goal       = (const float*)d_in[3];
    const float* observed   = (const float*)d_in[4];

    float* out = (float*)d_out;
    float* out_state   = out;
    float* out_cost    = out + NPED*4;
    float* out_stacked = out + NPED*4 + 1;

    forces_prop_stack_kernel<<<NPED/8, 256>>>(state, goal, stacked_in,
                                              out_state, out_stacked);
    cost_partial_kernel<<<NBLKB, 128>>>(observed, out_state);
    cost_final_kernel<<<1, 32>>>(state, goal, cost_in, out_state, out_cost);
}

// round 15
// speedup vs baseline: 1.2503x; 1.0264x over previous
#include <cuda_runtime.h>

#define NPED  4096
#define TILE  2048          // j's per smem tile -> 1024 float4 entries (16KB)
#define NBLKB 32            // cost blocks

#define DT        0.4f
#define K_ATTR    2.0f
#define PED_SPEED 1.0f
#define INV_MASS  (1.0f/60.0f)
#define EPS       1e-8f
#define A_COST    5.0f
#define B_COST    2.0f
// 10*exp((0.6-dist)/0.71) = exp2(C1 - dist*C2)
#define C2_EXP 2.0319648f
#define C1_EXP 4.5411053f

__device__ unsigned int g_ticket = 0;
__device__ float g_dev_part[NBLKB];
__device__ float g_blm_part[NBLKB];

__device__ __forceinline__ float ex2_approx(float x) {
    float r; asm("ex2.approx.f32 %0, %1;" : "=f"(r) : "f"(x)); return r;
}
__device__ __forceinline__ float rsqrt_approx(float x) {
    float r; asm("rsqrt.approx.f32 %0, %1;" : "=f"(r) : "f"(x)); return r;
}
__device__ __forceinline__ unsigned long long pack2(float lo, float hi) {
    unsigned long long r; asm("mov.b64 %0, {%1, %2};" : "=l"(r) : "f"(lo), "f"(hi));
    return r;
}

// Kernel A: stacked copy + forces + propagation.
// 512 blocks x 256 threads; warp w of block b owns pedestrian i = b*8+w.
// Inner loop: SoA-packed f32x2 math, 2 j-pairs per LDS.128.
__global__ void __launch_bounds__(256) forces_prop_stack_kernel(
    const float* __restrict__ state,       // [N,4]
    const float* __restrict__ goal,        // [N,2]
    const float* __restrict__ stacked_in,  // [N*4]
    float* __restrict__ out_state,         // [N,4]
    float* __restrict__ out_stacked)       // [2*N*4] (4B-aligned only)
{
    __shared__ float4 sxy[TILE / 2];       // {x_2k, x_2k+1, y_2k, y_2k+1}

    const int tid  = threadIdx.x;
    const int lane = tid & 31;
    const int i    = blockIdx.x * 8 + (tid >> 5);

    // fused concat copy
    {
        int g = blockIdx.x * 256 + tid;
        if (g < NPED * 4) {
            out_stacked[g]            = stacked_in[g];
            out_stacked[NPED * 4 + g] = state[g];
        }
    }

    const float4* __restrict__ srow = (const float4*)state;  // {px,py,vx,vy}
    const float4 si = srow[i];
    const float xi = si.x, yi = si.y;

    const unsigned long long nxi2 = pack2(-xi, -xi);
    const unsigned long long nyi2 = pack2(-yi, -yi);
    const unsigned long long eps2 = pack2(EPS, EPS);
    const unsigned long long c1p  = pack2(C1_EXP, C1_EXP);
    const unsigned long long nc2p = pack2(-C2_EXP, -C2_EXP);

    unsigned long long fxn = 0ull, fyn = 0ull;   // packed negated force accums

    #pragma unroll
    for (int t = 0; t < NPED / TILE; t++) {
        // stage: entry k holds x/y of rows (t*TILE + 2k, +2k+1)
        #pragma unroll
        for (int k = tid; k < TILE / 2; k += 256) {
            float4 a = srow[t * TILE + 2 * k];
            float4 b = srow[t * TILE + 2 * k + 1];
            sxy[k] = make_float4(a.x, b.x, a.y, b.y);
        }
        __syncthreads();

        #pragma unroll 8
        for (int jj = lane; jj < TILE / 2; jj += 32) {
            float4 q = sxy[jj];                       // one LDS.128, 2 pairs
            unsigned long long pxp = pack2(q.x, q.y);
            unsigned long long pyp = pack2(q.z, q.w);
            unsigned long long dxn, dyn, d2a_, d2p, distp, argp, rdp, ep, coefp;
            asm("add.rn.f32x2 %0, %1, %2;" : "=l"(dxn) : "l"(pxp), "l"(nxi2)); // px-xi
            asm("add.rn.f32x2 %0, %1, %2;" : "=l"(dyn) : "l"(pyp), "l"(nyi2)); // py-yi
            asm("fma.rn.f32x2 %0, %1, %1, %2;" : "=l"(d2a_) : "l"(dxn), "l"(eps2));
            asm("fma.rn.f32x2 %0, %1, %1, %2;" : "=l"(d2p)  : "l"(dyn), "l"(d2a_));
            float d2a, d2b;
            asm("mov.b64 {%0, %1}, %2;" : "=f"(d2a), "=f"(d2b) : "l"(d2p));
            rdp = pack2(rsqrt_approx(d2a), rsqrt_approx(d2b));
            asm("mul.rn.f32x2 %0, %1, %2;" : "=l"(distp) : "l"(d2p), "l"(rdp)); // sqrt
            asm("fma.rn.f32x2 %0, %1, %2, %3;" : "=l"(argp)
                : "l"(distp), "l"(nc2p), "l"(c1p));
            float aa, ab;
            asm("mov.b64 {%0, %1}, %2;" : "=f"(aa), "=f"(ab) : "l"(argp));
            ep = pack2(ex2_approx(aa), ex2_approx(ab));
            asm("mul.rn.f32x2 %0, %1, %2;" : "=l"(coefp) : "l"(ep), "l"(rdp));
            // j==i lane: dxn=dyn=0 exactly -> contributes exactly 0
            asm("fma.rn.f32x2 %0, %1, %2, %0;" : "+l"(fxn) : "l"(coefp), "l"(dxn));
            asm("fma.rn.f32x2 %0, %1, %2, %0;" : "+l"(fyn) : "l"(coefp), "l"(dyn));
        }
        __syncthreads();
    }

    float fxl, fxh, fyl, fyh;
    asm("mov.b64 {%0, %1}, %2;" : "=f"(fxl), "=f"(fxh) : "l"(fxn));
    asm("mov.b64 {%0, %1}, %2;" : "=f"(fyl), "=f"(fyh) : "l"(fyn));
    float fx = -(fxl + fxh);     // un-negate
    float fy = -(fyl + fyh);

    #pragma unroll
    for (int o = 16; o > 0; o >>= 1) {
        fx += __shfl_xor_sync(0xffffffffu, fx, o);
        fy += __shfl_xor_sync(0xffffffffu, fy, o);
    }

    if (lane == 0) {
        const float vx = si.z, vy = si.w;
        const float2 gl = ((const float2*)goal)[i];

        float tgx = gl.x - xi, tgy = gl.y - yi;
        float dg2 = fmaf(tgx, tgx, fmaf(tgy, tgy, EPS));
        float rdg = rsqrt_approx(dg2);
        float afx = K_ATTR * fmaf(PED_SPEED * tgx, rdg, -vx);
        float afy = K_ATTR * fmaf(PED_SPEED * tgy, rdg, -vy);

        float Fx = fmaf(fx, INV_MASS, afx);
        float Fy = fmaf(fy, INV_MASS, afy);

        float npx = xi + vx * DT + 0.5f * Fx * (DT * DT);
        float npy = yi + vy * DT + 0.5f * Fy * (DT * DT);
        float nvx = fmaf(Fx, DT, vx);
        float nvy = fmaf(Fy, DT, vy);
        float spd = sqrtf(fmaf(nvx, nvx, fmaf(nvy, nvy, EPS)));
        float scale = fminf(1.0f, PED_SPEED / spd);

        ((float4*)out_state)[i] = make_float4(npx, npy, nvx * scale, nvy * scale);
    }
}

// Kernel B: cost partials + ticketed finalize. 32 blocks x 128 threads.
__global__ void __launch_bounds__(128) cost_kernel(
    const float* __restrict__ state,
    const float* __restrict__ goal,
    const float* __restrict__ observed,    // [N,4]
    const float* __restrict__ cost_in,
    const float* __restrict__ out_state,   // [N,4]
    float* __restrict__ cost_out)
{
    const int tid  = threadIdx.x;
    const int p    = blockIdx.x * 128 + tid;
    const int lane = tid & 31;
    const int w    = tid >> 5;
    __shared__ float s_d[4], s_b[4];
    __shared__ int s_last;

    const float rx = out_state[0];
    const float ry = out_state[1];

    float dev = 0.0f, blm = 0.0f;
    if (p >= 1) {   // peds are rows 1..N-1
        float px = out_state[p*4 + 0];
        float py = out_state[p*4 + 1];
        float ox = observed[p*4 + 0];
        float oy = observed[p*4 + 1];
        float ddx = px - ox, ddy = py - oy;
        dev = sqrtf(fmaf(ddx, ddx, fmaf(ddy, ddy, EPS)));
        float bx = px - rx, by = py - ry;
        float d = sqrtf(fmaf(bx, bx, fmaf(by, by, EPS)));
        blm = ex2_approx(-d * 1.4426950f);   // exp(-d), E_COST=1
    }

    #pragma unroll
    for (int o = 16; o > 0; o >>= 1) {
        dev += __shfl_xor_sync(0xffffffffu, dev, o);
        blm += __shfl_xor_sync(0xffffffffu, blm, o);
    }
    if (lane == 0) { s_d[w] = dev; s_b[w] = blm; }
    __syncthreads();
    if (tid == 0) {
        g_dev_part[blockIdx.x] = s_d[0] + s_d[1] + s_d[2] + s_d[3];
        g_blm_part[blockIdx.x] = s_b[0] + s_b[1] + s_b[2] + s_b[3];
    }

    __threadfence();
    if (tid == 0) {
        unsigned int t = atomicAdd(&g_ticket, 1u);
        s_last = (t == NBLKB - 1) ? 1 : 0;
    }
    __syncthreads();

    if (s_last && tid < 32) {
        __threadfence();
        float dv = __ldcg(&g_dev_part[tid]);
        float bl = __ldcg(&g_blm_part[tid]);
        #pragma unroll
        for (int o = 16; o > 0; o >>= 1) {
            dv += __shfl_xor_sync(0xffffffffu, dv, o);
            bl += __shfl_xor_sync(0xffffffffu, bl, o);
        }
        if (tid == 0) {
            float ix = state[0], iy = state[1];
            float gx = goal[0],  gy = goal[1];
            float d1x = ix - gx, d1y = iy - gy;
            float d2x = rx - gx, d2y = ry - gy;
            float pg = sqrtf(fmaf(d1x, d1x, fmaf(d1y, d1y, EPS)))
                     - sqrtf(fmaf(d2x, d2x, fmaf(d2y, d2y, EPS)));
            cost_out[0] = cost_in[0] + A_COST * dv + B_COST * bl - pg;
            g_ticket = 0;   // reset for next graph replay
            __threadfence();
        }
    }
}

extern "C" void kernel_launch(void* const* d_in, const int* in_sizes, int n_in,
                              void* d_out, int out_size) {
    const float* state      = (const float*)d_in[0];
    const float* cost_in    = (const float*)d_in[1];
    const float* stacked_in = (const float*)d_in[2];
    const float* goal       = (const float*)d_in[3];
    const float* observed   = (const float*)d_in[4];

    float* out = (float*)d_out;
    float* out_state   = out;
    float* out_cost    = out + NPED*4;
    float* out_stacked = out + NPED*4 + 1;

    forces_prop_stack_kernel<<<NPED/8, 256>>>(state, goal, stacked_in,
                                              out_state, out_stacked);
    cost_kernel<<<NBLKB, 128>>>(state, goal, observed, cost_in,
                                out_state, out_cost);
}

// round 16
// speedup vs baseline: 1.3704x; 1.0960x over previous
#include <cuda_runtime.h>

#define NPED  4096
#define HALF  2048          // j's per block (one half)
#define NBLKB 32            // cost-partial blocks

#define DT        0.4f
#define K_ATTR    2.0f
#define PED_SPEED 1.0f
#define INV_MASS  (1.0f/60.0f)
#define EPS       1e-8f
#define A_COST    5.0f
#define B_COST    2.0f
// 10*exp((0.6-dist)/0.71) = exp2(C1 - dist*C2)
#define C2_EXP 2.0319648f
#define C1_EXP 4.5411053f

__device__ float2 g_fpart[NPED * 2];     // per-(ped, half) force partials
__device__ float  g_dev_part[NBLKB];
__device__ float  g_blm_part[NBLKB];

__device__ __forceinline__ float ex2_approx(float x) {
    float r; asm("ex2.approx.f32 %0, %1;" : "=f"(r) : "f"(x)); return r;
}
__device__ __forceinline__ float rsqrt_approx(float x) {
    float r; asm("rsqrt.approx.f32 %0, %1;" : "=f"(r) : "f"(x)); return r;
}
__device__ __forceinline__ unsigned long long pack2(float lo, float hi) {
    unsigned long long r; asm("mov.b64 %0, {%1, %2};" : "=l"(r) : "f"(lo), "f"(hi));
    return r;
}

// Kernel A: repulsion force partials (+ fused stacked copy).
// 1024 blocks x 256 threads. Block b: half h = b&1, peds i = (b>>1)*8 + w.
// Each block stages its 2048-j half as 1024 packed float4 entries (16KB)
// and computes each warp's partial force over that half. No fences.
__global__ void __launch_bounds__(256) forces_partial_kernel(
    const float* __restrict__ state,       // [N,4]
    const float* __restrict__ stacked_in,  // [N*4]
    float* __restrict__ out_stacked)       // [2*N*4] (4B-aligned only)
{
    __shared__ float4 sxy[HALF / 2];       // {x_2k, x_2k+1, y_2k, y_2k+1}

    const int tid  = threadIdx.x;
    const int lane = tid & 31;
    const int h    = blockIdx.x & 1;
    const int i    = (blockIdx.x >> 1) * 8 + (tid >> 5);
    const int base = h * HALF;

    // fused concat copy: blocks 0..63 cover 16384 floats each half
    {
        int g = blockIdx.x * 256 + tid;
        if (g < NPED * 4) {
            out_stacked[g]            = stacked_in[g];
            out_stacked[NPED * 4 + g] = state[g];
        }
    }

    const float4* __restrict__ srow = (const float4*)state;  // {px,py,vx,vy}
    const float4 si = srow[i];
    const float xi = si.x, yi = si.y;

    // stage this block's half
    #pragma unroll
    for (int k = tid; k < HALF / 2; k += 256) {
        float4 a = srow[base + 2 * k];
        float4 b = srow[base + 2 * k + 1];
        sxy[k] = make_float4(a.x, b.x, a.y, b.y);
    }
    __syncthreads();

    const unsigned long long nxi2 = pack2(-xi, -xi);
    const unsigned long long nyi2 = pack2(-yi, -yi);
    const unsigned long long eps2 = pack2(EPS, EPS);
    const unsigned long long c1p  = pack2(C1_EXP, C1_EXP);
    const unsigned long long nc2p = pack2(-C2_EXP, -C2_EXP);

    unsigned long long fxn = 0ull, fyn = 0ull;   // packed negated force accums

    #pragma unroll 8
    for (int jj = lane; jj < HALF / 2; jj += 32) {
        float4 q = sxy[jj];                       // one LDS.128, 2 pairs
        unsigned long long pxp = pack2(q.x, q.y);
        unsigned long long pyp = pack2(q.z, q.w);
        unsigned long long dxn, dyn, d2a_, d2p, distp, argp, rdp, ep, coefp;
        asm("add.rn.f32x2 %0, %1, %2;" : "=l"(dxn) : "l"(pxp), "l"(nxi2)); // px-xi
        asm("add.rn.f32x2 %0, %1, %2;" : "=l"(dyn) : "l"(pyp), "l"(nyi2)); // py-yi
        asm("fma.rn.f32x2 %0, %1, %1, %2;" : "=l"(d2a_) : "l"(dxn), "l"(eps2));
        asm("fma.rn.f32x2 %0, %1, %1, %2;" : "=l"(d2p)  : "l"(dyn), "l"(d2a_));
        float d2a, d2b;
        asm("mov.b64 {%0, %1}, %2;" : "=f"(d2a), "=f"(d2b) : "l"(d2p));
        rdp = pack2(rsqrt_approx(d2a), rsqrt_approx(d2b));
        asm("mul.rn.f32x2 %0, %1, %2;" : "=l"(distp) : "l"(d2p), "l"(rdp)); // sqrt
        asm("fma.rn.f32x2 %0, %1, %2, %3;" : "=l"(argp)
            : "l"(distp), "l"(nc2p), "l"(c1p));
        float aa, ab;
        asm("mov.b64 {%0, %1}, %2;" : "=f"(aa), "=f"(ab) : "l"(argp));
        ep = pack2(ex2_approx(aa), ex2_approx(ab));
        asm("mul.rn.f32x2 %0, %1, %2;" : "=l"(coefp) : "l"(ep), "l"(rdp));
        // j==i entry: dxn=dyn=0 exactly -> contributes exactly 0
        asm("fma.rn.f32x2 %0, %1, %2, %0;" : "+l"(fxn) : "l"(coefp), "l"(dxn));
        asm("fma.rn.f32x2 %0, %1, %2, %0;" : "+l"(fyn) : "l"(coefp), "l"(dyn));
    }

    float fxl, fxh, fyl, fyh;
    asm("mov.b64 {%0, %1}, %2;" : "=f"(fxl), "=f"(fxh) : "l"(fxn));
    asm("mov.b64 {%0, %1}, %2;" : "=f"(fyl), "=f"(fyh) : "l"(fyn));
    float fx = -(fxl + fxh);     // un-negate
    float fy = -(fyl + fyh);

    #pragma unroll
    for (int o = 16; o > 0; o >>= 1) {
        fx += __shfl_xor_sync(0xffffffffu, fx, o);
        fy += __shfl_xor_sync(0xffffffffu, fy, o);
    }

    if (lane == 0)
        g_fpart[i * 2 + h] = make_float2(fx, fy);
}

// Kernel B: combine halves + attractive force + propagation.
// 16 blocks x 256 threads, one pedestrian per thread.
__global__ void __launch_bounds__(256) propagate_kernel(
    const float* __restrict__ state,   // [N,4]
    const float* __restrict__ goal,    // [N,2]
    float* __restrict__ out_state)     // [N,4]
{
    const int i = blockIdx.x * 256 + threadIdx.x;

    float2 p0 = g_fpart[i * 2 + 0];
    float2 p1 = g_fpart[i * 2 + 1];
    float fx = p0.x + p1.x;            // fixed order: deterministic
    float fy = p0.y + p1.y;

    const float4 si = ((const float4*)state)[i];
    const float xi = si.x, yi = si.y, vx = si.z, vy = si.w;
    const float2 gl = ((const float2*)goal)[i];

    float tgx = gl.x - xi, tgy = gl.y - yi;
    float dg2 = fmaf(tgx, tgx, fmaf(tgy, tgy, EPS));
    float rdg = rsqrt_approx(dg2);
    float afx = K_ATTR * fmaf(PED_SPEED * tgx, rdg, -vx);
    float afy = K_ATTR * fmaf(PED_SPEED * tgy, rdg, -vy);

    float Fx = fmaf(fx, INV_MASS, afx);
    float Fy = fmaf(fy, INV_MASS, afy);

    float npx = xi + vx * DT + 0.5f * Fx * (DT * DT);
    float npy = yi + vy * DT + 0.5f * Fy * (DT * DT);
    float nvx = fmaf(Fx, DT, vx);
    float nvy = fmaf(Fy, DT, vy);
    float spd = sqrtf(fmaf(nvx, nvx, fmaf(nvy, nvy, EPS)));
    float scale = fminf(1.0f, PED_SPEED / spd);

    ((float4*)out_state)[i] = make_float4(npx, npy, nvx * scale, nvy * scale);
}

// Kernel C: cost partials. 32 blocks x 128 threads, one ped per thread.
__global__ void __launch_bounds__(128) cost_partial_kernel(
    const float* __restrict__ observed,    // [N,4]
    const float* __restrict__ out_state)   // [N,4]
{
    const int tid = threadIdx.x;
    const int p   = blockIdx.x * 128 + tid;
    const int lane = tid & 31;
    const int w    = tid >> 5;
    __shared__ float s_d[4], s_b[4];

    const float rx = out_state[0];
    const float ry = out_state[1];

    float dev = 0.0f, blm = 0.0f;
    if (p >= 1) {   // peds are rows 1..N-1
        float px = out_state[p*4 + 0];
        float py = out_state[p*4 + 1];
        float ox = observed[p*4 + 0];
        float oy = observed[p*4 + 1];
        float ddx = px - ox, ddy = py - oy;
        dev = sqrtf(fmaf(ddx, ddx, fmaf(ddy, ddy, EPS)));
        float bx = px - rx, by = py - ry;
        float d = sqrtf(fmaf(bx, bx, fmaf(by, by, EPS)));
        blm = ex2_approx(-d * 1.4426950f);   // exp(-d), E_COST=1
    }

    #pragma unroll
    for (int o = 16; o > 0; o >>= 1) {
        dev += __shfl_xor_sync(0xffffffffu, dev, o);
        blm += __shfl_xor_sync(0xffffffffu, blm, o);
    }
    if (lane == 0) { s_d[w] = dev; s_b[w] = blm; }
    __syncthreads();
    if (tid == 0) {
        g_dev_part[blockIdx.x] = s_d[0] + s_d[1] + s_d[2] + s_d[3];
        g_blm_part[blockIdx.x] = s_b[0] + s_b[1] + s_b[2] + s_b[3];
    }
}

// Kernel D: finalize cost. 1 block, 32 threads.
__global__ void __launch_bounds__(32) cost_final_kernel(
    const float* __restrict__ state,
    const float* __restrict__ goal,
    const float* __restrict__ cost_in,
    const float* __restrict__ out_state,
    float* __restrict__ cost_out)
{
    const int lane = threadIdx.x;
    float dev = g_dev_part[lane];
    float blm = g_blm_part[lane];
    #pragma unroll
    for (int o = 16; o > 0; o >>= 1) {
        dev += __shfl_xor_sync(0xffffffffu, dev, o);
        blm += __shfl_xor_sync(0xffffffffu, blm, o);
    }
    if (lane == 0) {
        float rx = out_state[0], ry = out_state[1];
        float ix = state[0], iy = state[1];
        float gx = goal[0],  gy = goal[1];
        float d1x = ix - gx, d1y = iy - gy;
        float d2x = rx - gx, d2y = ry - gy;
        float pg = sqrtf(fmaf(d1x, d1x, fmaf(d1y, d1y, EPS)))
                 - sqrtf(fmaf(d2x, d2x, fmaf(d2y, d2y, EPS)));
        cost_out[0] = cost_in[0] + A_COST * dev + B_COST * blm - pg;
    }
}

extern "C" void kernel_launch(void* const* d_in, const int* in_sizes, int n_in,
                              void* d_out, int out_size) {
    const float* state      = (const float*)d_in[0];
    const float* cost_in    = (const float*)d_in[1];
    const float* stacked_in = (const float*)d_in[2];
    const float* goal       = (const float*)d_in[3];
    const float* observed   = (const float*)d_in[4];

    float* out = (float*)d_out;
    float* out_state   = out;
    float* out_cost    = out + NPED*4;
    float* out_stacked = out + NPED*4 + 1;

    forces_partial_kernel<<<NPED/8 * 2, 256>>>(state, stacked_in, out_stacked);
    propagate_kernel<<<NPED/256, 256>>>(state, goal, out_state);
    cost_partial_kernel<<<NBLKB, 128>>>(observed, out_state);
    cost_final_kernel<<<1, 32>>>(state, goal, cost_in, out_state, out_cost);
}

// round 17
// speedup vs baseline: 1.3725x; 1.0015x over previous
#include <cuda_runtime.h>

#define NPED  4096
#define HALF  2048          // j's per forces block (one half)

#define DT        0.4f
#define K_ATTR    2.0f
#define PED_SPEED 1.0f
#define INV_MASS  (1.0f/60.0f)
#define EPS       1e-8f
#define A_COST    5.0f
#define B_COST    2.0f
// 10*exp((0.6-dist)/0.71) = exp2(C1 - dist*C2)
#define C2_EXP 2.0319648f
#define C1_EXP 4.5411053f

__device__ float2 g_fpart[NPED * 2];     // per-(ped, half) force partials

__device__ __forceinline__ float ex2_approx(float x) {
    float r; asm("ex2.approx.f32 %0, %1;" : "=f"(r) : "f"(x)); return r;
}
__device__ __forceinline__ float rsqrt_approx(float x) {
    float r; asm("rsqrt.approx.f32 %0, %1;" : "=f"(r) : "f"(x)); return r;
}
__device__ __forceinline__ unsigned long long pack2(float lo, float hi) {
    unsigned long long r; asm("mov.b64 %0, {%1, %2};" : "=l"(r) : "f"(lo), "f"(hi));
    return r;
}

// Kernel A: repulsion force partials (+ fused stacked copy).
// 1024 blocks x 256 threads. Block b: half h = b&1, peds i = (b>>1)*8 + w.
__global__ void __launch_bounds__(256) forces_partial_kernel(
    const float* __restrict__ state,       // [N,4]
    const float* __restrict__ stacked_in,  // [N*4]
    float* __restrict__ out_stacked)       // [2*N*4] (4B-aligned only)
{
    __shared__ float4 sxy[HALF / 2];       // {x_2k, x_2k+1, y_2k, y_2k+1}

    const int tid  = threadIdx.x;
    const int lane = tid & 31;
    const int h    = blockIdx.x & 1;
    const int i    = (blockIdx.x >> 1) * 8 + (tid >> 5);
    const int base = h * HALF;

    // fused concat copy: blocks 0..63 cover 16384 floats each half
    {
        int g = blockIdx.x * 256 + tid;
        if (g < NPED * 4) {
            out_stacked[g]            = stacked_in[g];
            out_stacked[NPED * 4 + g] = state[g];
        }
    }

    const float4* __restrict__ srow = (const float4*)state;  // {px,py,vx,vy}
    const float4 si = srow[i];
    const float xi = si.x, yi = si.y;

    // stage this block's half
    #pragma unroll
    for (int k = tid; k < HALF / 2; k += 256) {
        float4 a = srow[base + 2 * k];
        float4 b = srow[base + 2 * k + 1];
        sxy[k] = make_float4(a.x, b.x, a.y, b.y);
    }
    __syncthreads();

    const unsigned long long nxi2 = pack2(-xi, -xi);
    const unsigned long long nyi2 = pack2(-yi, -yi);
    const unsigned long long eps2 = pack2(EPS, EPS);
    const unsigned long long c1p  = pack2(C1_EXP, C1_EXP);
    const unsigned long long nc2p = pack2(-C2_EXP, -C2_EXP);

    unsigned long long fxn = 0ull, fyn = 0ull;   // packed negated force accums

    #pragma unroll 8
    for (int jj = lane; jj < HALF / 2; jj += 32) {
        float4 q = sxy[jj];                       // one LDS.128, 2 pairs
        unsigned long long pxp = pack2(q.x, q.y);
        unsigned long long pyp = pack2(q.z, q.w);
        unsigned long long dxn, dyn, d2a_, d2p, distp, argp, rdp, ep, coefp;
        asm("add.rn.f32x2 %0, %1, %2;" : "=l"(dxn) : "l"(pxp), "l"(nxi2)); // px-xi
        asm("add.rn.f32x2 %0, %1, %2;" : "=l"(dyn) : "l"(pyp), "l"(nyi2)); // py-yi
        asm("fma.rn.f32x2 %0, %1, %1, %2;" : "=l"(d2a_) : "l"(dxn), "l"(eps2));
        asm("fma.rn.f32x2 %0, %1, %1, %2;" : "=l"(d2p)  : "l"(dyn), "l"(d2a_));
        float d2a, d2b;
        asm("mov.b64 {%0, %1}, %2;" : "=f"(d2a), "=f"(d2b) : "l"(d2p));
        rdp = pack2(rsqrt_approx(d2a), rsqrt_approx(d2b));
        asm("mul.rn.f32x2 %0, %1, %2;" : "=l"(distp) : "l"(d2p), "l"(rdp)); // sqrt
        asm("fma.rn.f32x2 %0, %1, %2, %3;" : "=l"(argp)
            : "l"(distp), "l"(nc2p), "l"(c1p));
        float aa, ab;
        asm("mov.b64 {%0, %1}, %2;" : "=f"(aa), "=f"(ab) : "l"(argp));
        ep = pack2(ex2_approx(aa), ex2_approx(ab));
        asm("mul.rn.f32x2 %0, %1, %2;" : "=l"(coefp) : "l"(ep), "l"(rdp));
        // j==i entry: dxn=dyn=0 exactly -> contributes exactly 0
        asm("fma.rn.f32x2 %0, %1, %2, %0;" : "+l"(fxn) : "l"(coefp), "l"(dxn));
        asm("fma.rn.f32x2 %0, %1, %2, %0;" : "+l"(fyn) : "l"(coefp), "l"(dyn));
    }

    float fxl, fxh, fyl, fyh;
    asm("mov.b64 {%0, %1}, %2;" : "=f"(fxl), "=f"(fxh) : "l"(fxn));
    asm("mov.b64 {%0, %1}, %2;" : "=f"(fyl), "=f"(fyh) : "l"(fyn));
    float fx = -(fxl + fxh);     // un-negate
    float fy = -(fyl + fyh);

    #pragma unroll
    for (int o = 16; o > 0; o >>= 1) {
        fx += __shfl_xor_sync(0xffffffffu, fx, o);
        fy += __shfl_xor_sync(0xffffffffu, fy, o);
    }

    if (lane == 0)
        g_fpart[i * 2 + h] = make_float2(fx, fy);
}

// helper: total force for ped i from partials + attractive term
__device__ __forceinline__ void total_force(
    int i, const float4 si, float2 gl, float& Fx, float& Fy)
{
    float2 p0 = g_fpart[i * 2 + 0];
    float2 p1 = g_fpart[i * 2 + 1];
    float fx = p0.x + p1.x;            // fixed order: deterministic
    float fy = p0.y + p1.y;

    float tgx = gl.x - si.x, tgy = gl.y - si.y;
    float dg2 = fmaf(tgx, tgx, fmaf(tgy, tgy, EPS));
    float rdg = rsqrt_approx(dg2);
    float afx = K_ATTR * fmaf(PED_SPEED * tgx, rdg, -si.z);
    float afy = K_ATTR * fmaf(PED_SPEED * tgy, rdg, -si.w);

    Fx = fmaf(fx, INV_MASS, afx);
    Fy = fmaf(fy, INV_MASS, afy);
}

// Kernel Z: propagate + cost, single block (no cross-block deps, no fences).
// 1024 threads; thread t handles peds t, t+1024, t+2048, t+3072.
__global__ void __launch_bounds__(1024) propagate_cost_kernel(
    const float* __restrict__ state,      // [N,4]
    const float* __restrict__ goal,       // [N,2]
    const float* __restrict__ observed,   // [N,4]
    const float* __restrict__ cost_in,    // [1]
    float* __restrict__ out_state,        // [N,4]
    float* __restrict__ cost_out)         // [1]
{
    __shared__ float s_rx, s_ry;
    __shared__ float s_d[32], s_b[32];

    const int tid  = threadIdx.x;
    const int lane = tid & 31;
    const int w    = tid >> 5;

    const float4* __restrict__ srow = (const float4*)state;
    const float2* __restrict__ grow = (const float2*)goal;

    // pre-phase: robot new pos (no vel clamp needed for position)
    if (tid == 0) {
        float4 s0 = srow[0];
        float Fx, Fy;
        total_force(0, s0, grow[0], Fx, Fy);
        s_rx = s0.x + s0.z * DT + 0.5f * Fx * (DT * DT);
        s_ry = s0.y + s0.w * DT + 0.5f * Fy * (DT * DT);
    }
    __syncthreads();
    const float rx = s_rx, ry = s_ry;

    float dev = 0.0f, blm = 0.0f;

    #pragma unroll
    for (int k = 0; k < NPED / 1024; k++) {
        const int i = tid + k * 1024;
        const float4 si = srow[i];
        float Fx, Fy;
        total_force(i, si, grow[i], Fx, Fy);

        float npx = si.x + si.z * DT + 0.5f * Fx * (DT * DT);
        float npy = si.y + si.w * DT + 0.5f * Fy * (DT * DT);
        float nvx = fmaf(Fx, DT, si.z);
        float nvy = fmaf(Fy, DT, si.w);
        float spd = sqrtf(fmaf(nvx, nvx, fmaf(nvy, nvy, EPS)));
        float scale = fminf(1.0f, PED_SPEED / spd);

        ((float4*)out_state)[i] = make_float4(npx, npy, nvx * scale, nvy * scale);

        if (i >= 1) {   // peds are rows 1..N-1
            float ox = observed[i*4 + 0];
            float oy = observed[i*4 + 1];
            float ddx = npx - ox, ddy = npy - oy;
            dev += sqrtf(fmaf(ddx, ddx, fmaf(ddy, ddy, EPS)));
            float bx = npx - rx, by = npy - ry;
            float d = sqrtf(fmaf(bx, bx, fmaf(by, by, EPS)));
            blm += ex2_approx(-d * 1.4426950f);   // exp(-d), E_COST=1
        }
    }

    // deterministic reduction: warp shuffle -> smem -> warp 0 in lane order
    #pragma unroll
    for (int o = 16; o > 0; o >>= 1) {
        dev += __shfl_xor_sync(0xffffffffu, dev, o);
        blm += __shfl_xor_sync(0xffffffffu, blm, o);
    }
    if (lane == 0) { s_d[w] = dev; s_b[w] = blm; }
    __syncthreads();

    if (w == 0) {
        float dv = s_d[lane];
        float bl = s_b[lane];
        #pragma unroll
        for (int o = 16; o > 0; o >>= 1) {
            dv += __shfl_xor_sync(0xffffffffu, dv, o);
            bl += __shfl_xor_sync(0xffffffffu, bl, o);
        }
        if (lane == 0) {
            float ix = state[0], iy = state[1];
            float gx = goal[0],  gy = goal[1];
            float d1x = ix - gx, d1y = iy - gy;
            float d2x = rx - gx, d2y = ry - gy;
            float pg = sqrtf(fmaf(d1x, d1x, fmaf(d1y, d1y, EPS)))
                     - sqrtf(fmaf(d2x, d2x, fmaf(d2y, d2y, EPS)));
            cost_out[0] = cost_in[0] + A_COST * dv + B_COST * bl - pg;
        }
    }
}

extern "C" void kernel_launch(void* const* d_in, const int* in_sizes, int n_in,
                              void* d_out, int out_size) {
    const float* state      = (const float*)d_in[0];
    const float* cost_in    = (const float*)d_in[1];
    const float* stacked_in = (const float*)d_in[2];
    const float* goal       = (const float*)d_in[3];
    const float* observed   = (const float*)d_in[4];

    float* out = (float*)d_out;
    float* out_state   = out;
    float* out_cost    = out + NPED*4;
    float* out_stacked = out + NPED*4 + 1;

    forces_partial_kernel<<<NPED/8 * 2, 256>>>(state, stacked_in, out_stacked);
    propagate_cost_kernel<<<1, 1024>>>(state, goal, observed, cost_in,
                                       out_state, out_cost);
}